// round 1
// baseline (speedup 1.0000x reference)
#include <cuda_runtime.h>
#include <cstdint>

// Problem constants
#define Bdim 4
#define Tdim 2048
#define Cdim 1024
#define Hn   16
#define HDim 64
#define MROWS (Bdim * Tdim)     // 8192
#define NQKV  (3 * Cdim)        // 3072

// Scratch (allocation-free rule: __device__ globals)
__device__ float g_qkv[(size_t)MROWS * NQKV];  // [8192, 3072]
__device__ float g_y[(size_t)MROWS * Cdim];    // [8192, 1024] attention output (pre-proj)

// ---------------------------------------------------------------------------
// SGEMM: C[M,N] = A[M,K] @ B[K,N] + bias[N]
// 128x128 block tile, BK=8, 256 threads, 8x8 per-thread microtile.
// M,N multiples of 128; K multiple of 8 (holds for all three calls).
// ---------------------------------------------------------------------------
template <int M, int N, int K>
__device__ __forceinline__ void sgemm_bias_body(const float* __restrict__ A,
                                                const float* __restrict__ B,
                                                const float* __restrict__ bias,
                                                float* __restrict__ C) {
    __shared__ float As[8][128];   // transposed A tile: As[k][m]
    __shared__ float Bs[8][128];   // Bs[k][n]

    const int tid = threadIdx.x;
    const int tx  = tid & 15;      // 0..15 -> N
    const int ty  = tid >> 4;      // 0..15 -> M
    const int row0 = blockIdx.y * 128;
    const int col0 = blockIdx.x * 128;

    const int rowA = tid >> 1;           // 0..127
    const int colA = (tid & 1) * 4;      // 0 or 4
    const int rowB = tid >> 5;           // 0..7
    const int colB = (tid & 31) * 4;     // 0..124

    float acc[8][8];
#pragma unroll
    for (int i = 0; i < 8; i++)
#pragma unroll
        for (int j = 0; j < 8; j++) acc[i][j] = 0.f;

    const float* aptr = A + (size_t)(row0 + rowA) * K + colA;
    const float* bptr = B + (size_t)rowB * N + col0 + colB;

    for (int k0 = 0; k0 < K; k0 += 8) {
        float4 a = *(const float4*)(aptr + k0);
        float4 b = *(const float4*)(bptr + (size_t)k0 * N);
        As[colA + 0][rowA] = a.x;
        As[colA + 1][rowA] = a.y;
        As[colA + 2][rowA] = a.z;
        As[colA + 3][rowA] = a.w;
        *(float4*)&Bs[rowB][colB] = b;
        __syncthreads();

#pragma unroll
        for (int kk = 0; kk < 8; kk++) {
            float ar[8], br[8];
            *(float4*)&ar[0] = *(const float4*)&As[kk][ty * 8];
            *(float4*)&ar[4] = *(const float4*)&As[kk][ty * 8 + 4];
            *(float4*)&br[0] = *(const float4*)&Bs[kk][tx * 8];
            *(float4*)&br[4] = *(const float4*)&Bs[kk][tx * 8 + 4];
#pragma unroll
            for (int i = 0; i < 8; i++)
#pragma unroll
                for (int j = 0; j < 8; j++) acc[i][j] += ar[i] * br[j];
        }
        __syncthreads();
    }

    // epilogue: + bias, write
#pragma unroll
    for (int i = 0; i < 8; i++) {
        const int r = row0 + ty * 8 + i;
        float* crow = C + (size_t)r * N + col0 + tx * 8;
#pragma unroll
        for (int j = 0; j < 8; j += 4) {
            float4 o;
            o.x = acc[i][j + 0] + bias[col0 + tx * 8 + j + 0];
            o.y = acc[i][j + 1] + bias[col0 + tx * 8 + j + 1];
            o.z = acc[i][j + 2] + bias[col0 + tx * 8 + j + 2];
            o.w = acc[i][j + 3] + bias[col0 + tx * 8 + j + 3];
            *(float4*)(crow + j) = o;
        }
    }
}

__global__ void __launch_bounds__(256) k_qkv_gemm(const float* __restrict__ x,
                                                  const float* __restrict__ W,
                                                  const float* __restrict__ b) {
    sgemm_bias_body<MROWS, NQKV, Cdim>(x, W, b, g_qkv);
}

__global__ void __launch_bounds__(256) k_proj_gemm(const float* __restrict__ W,
                                                   const float* __restrict__ b,
                                                   float* __restrict__ out) {
    sgemm_bias_body<MROWS, Cdim, Cdim>(g_y, W, b, out);
}

// ---------------------------------------------------------------------------
// Causal flash attention (SIMT): 1 thread = 1 query row.
// Block = 128 threads = 128 consecutive queries of one (b,h).
// K/V streamed in 32-row smem tiles; q, acc, scores in registers;
// online softmax per thread.
// ---------------------------------------------------------------------------
__global__ void __launch_bounds__(128, 2) k_attn() {
    __shared__ float Ks[32][HDim];
    __shared__ float Vs[32][HDim];

    const int bh = blockIdx.x;          // 0..63
    const int b  = bh >> 4;             // /H
    const int h  = bh & 15;             // %H
    const int q0 = blockIdx.y * 128;
    const int qi = q0 + threadIdx.x;    // global query index in [0,T)

    // load q row (pre-scaled by 1/sqrt(HD) = 0.125)
    const float* qptr = g_qkv + (size_t)(b * Tdim + qi) * NQKV + h * HDim;
    float q[HDim];
#pragma unroll
    for (int d = 0; d < HDim; d += 4) {
        float4 t = *(const float4*)(qptr + d);
        q[d + 0] = t.x * 0.125f;
        q[d + 1] = t.y * 0.125f;
        q[d + 2] = t.z * 0.125f;
        q[d + 3] = t.w * 0.125f;
    }

    float acc[HDim];
#pragma unroll
    for (int d = 0; d < HDim; d++) acc[d] = 0.f;
    float m = -1e30f, l = 0.f;

    const int nT = (q0 + 128) / 32;     // tiles needed to cover keys <= q0+127
    for (int t = 0; t < nT; ++t) {
        const int k0 = t * 32;
        const float* kbase = g_qkv + (size_t)(b * Tdim + k0) * NQKV + Cdim + h * HDim;
        const float* vbase = kbase + Cdim;
#pragma unroll
        for (int i = threadIdx.x; i < 32 * 16; i += 128) {
            const int r = i >> 4;
            const int c = (i & 15) << 2;
            *(float4*)&Ks[r][c] = *(const float4*)(kbase + (size_t)r * NQKV + c);
            *(float4*)&Vs[r][c] = *(const float4*)(vbase + (size_t)r * NQKV + c);
        }
        __syncthreads();

        // scores
        float s[32];
#pragma unroll
        for (int j = 0; j < 32; j++) {
            float sj = 0.f;
#pragma unroll
            for (int d = 0; d < HDim; d += 4) {
                float4 kv = *(const float4*)&Ks[j][d];
                sj += q[d + 0] * kv.x;
                sj += q[d + 1] * kv.y;
                sj += q[d + 2] * kv.z;
                sj += q[d + 3] * kv.w;
            }
            // causal mask: by the time any masked key appears, m holds a real
            // score (tile 0 always has key 0 <= qi), so -1e30 gives exp -> 0.
            s[j] = (k0 + j <= qi) ? sj : -1e30f;
        }

        float mnew = m;
#pragma unroll
        for (int j = 0; j < 32; j++) mnew = fmaxf(mnew, s[j]);
        const float corr = __expf(m - mnew);
        l *= corr;
#pragma unroll
        for (int d = 0; d < HDim; d++) acc[d] *= corr;

#pragma unroll
        for (int j = 0; j < 32; j++) {
            const float p = __expf(s[j] - mnew);
            l += p;
#pragma unroll
            for (int d = 0; d < HDim; d += 4) {
                float4 v = *(const float4*)&Vs[j][d];
                acc[d + 0] += p * v.x;
                acc[d + 1] += p * v.y;
                acc[d + 2] += p * v.z;
                acc[d + 3] += p * v.w;
            }
        }
        m = mnew;
        __syncthreads();
    }

    const float inv = 1.f / l;
    float* optr = g_y + (size_t)(b * Tdim + qi) * Cdim + h * HDim;
#pragma unroll
    for (int d = 0; d < HDim; d += 4) {
        float4 o;
        o.x = acc[d + 0] * inv;
        o.y = acc[d + 1] * inv;
        o.z = acc[d + 2] * inv;
        o.w = acc[d + 3] * inv;
        *(float4*)(optr + d) = o;
    }
}

// ---------------------------------------------------------------------------
// Launch
// ---------------------------------------------------------------------------
extern "C" void kernel_launch(void* const* d_in, const int* in_sizes, int n_in,
                              void* d_out, int out_size) {
    const float* x      = (const float*)d_in[0];  // [B,T,C]
    const float* W_attn = (const float*)d_in[1];  // [C,3C]
    const float* b_attn = (const float*)d_in[2];  // [3C]
    const float* W_proj = (const float*)d_in[3];  // [C,C]
    const float* b_proj = (const float*)d_in[4];  // [C]
    float* out = (float*)d_out;                   // [B,T,C]

    // 1) QKV projection: [8192,1024] @ [1024,3072] + bias -> g_qkv
    {
        dim3 grid(NQKV / 128, MROWS / 128);  // (24, 64)
        k_qkv_gemm<<<grid, 256>>>(x, W_attn, b_attn);
    }
    // 2) causal flash attention -> g_y
    {
        dim3 grid(Bdim * Hn, Tdim / 128);    // (64, 16)
        k_attn<<<grid, 128>>>();
    }
    // 3) output projection: [8192,1024] @ [1024,1024] + bias -> out
    {
        dim3 grid(Cdim / 128, MROWS / 128);  // (8, 64)
        k_proj_gemm<<<grid, 256>>>(W_proj, b_proj, out);
    }
}